// round 10
// baseline (speedup 1.0000x reference)
#include <cuda_runtime.h>
#include <math.h>

#define CH 64
#define MAX_NODES 50000
#define NPB 96        // nodes per GEMM tile
#define ASTR 97       // A tile row stride in floats (conflict-free scalar reads)

// Scratch for the scatter-accumulated, scaled source features.
__device__ float g_buf[MAX_NODES * CH];
// 1 if edge_index buffer is int64, 0 if int32 (probed on device each run).
__device__ int g_is64;

// ---------------------------------------------------------------------------
// Kernel 0: probe edge_index dtype with one warp. int64 little-endian with
// values < 2^31 => every odd 32-bit word zero; random int32 can't give 32
// consecutive zeros there.
// ---------------------------------------------------------------------------
__global__ void probe_kernel(const int* __restrict__ ei32) {
    int nz = (ei32[2 * threadIdx.x + 1] != 0) ? 1 : 0;
    unsigned any = __ballot_sync(0xffffffffu, nz);
    if (threadIdx.x == 0) g_is64 = (any == 0u) ? 1 : 0;
}

// ---------------------------------------------------------------------------
// Kernel 1: edge scatter.  g_buf[dst] += ||edge_attr[e]|| * x[src]
// 16 threads per edge, one float4 per thread; leader loads metadata.
// No smem -> occupancy unconstrained; L2/LTS-bound (near its traffic floor).
// ---------------------------------------------------------------------------
__global__ void __launch_bounds__(256) edge_scatter_kernel(
    const float* __restrict__ x,
    const void* __restrict__ ei_raw,
    const float* __restrict__ ea,
    int E, int N)
{
    int t = blockIdx.x * blockDim.x + threadIdx.x;
    int e = t >> 4;
    if (e >= E) return;
    int lane = threadIdx.x & 15;
    int grpleader = threadIdx.x & 16;

    int src = 0, dst = 0;
    float scale = 0.f;
    if (lane == 0) {
        if (g_is64) {
            const long long* ei = (const long long*)ei_raw;
            src = (int)__ldg(&ei[e]);
            dst = (int)__ldg(&ei[E + e]);
        } else {
            const int* ei = (const int*)ei_raw;
            src = __ldg(&ei[e]);
            dst = __ldg(&ei[E + e]);
        }
        float a0 = __ldg(&ea[3 * e + 0]);
        float a1 = __ldg(&ea[3 * e + 1]);
        float a2 = __ldg(&ea[3 * e + 2]);
        scale = sqrtf(a0 * a0 + a1 * a1 + a2 * a2);
    }
    src   = __shfl_sync(0xffffffffu, src,   grpleader);
    dst   = __shfl_sync(0xffffffffu, dst,   grpleader);
    scale = __shfl_sync(0xffffffffu, scale, grpleader);

    if ((unsigned)src >= (unsigned)N || (unsigned)dst >= (unsigned)N) return;

    float4 v = __ldg(reinterpret_cast<const float4*>(x + (size_t)src * CH) + lane);
    v.x *= scale; v.y *= scale; v.z *= scale; v.w *= scale;

    float* addr = g_buf + (size_t)dst * CH + lane * 4;
    asm volatile("red.global.add.v4.f32 [%0], {%1, %2, %3, %4};"
                 :: "l"(addr), "f"(v.x), "f"(v.y), "f"(v.z), "f"(v.w)
                 : "memory");
}

// ---------------------------------------------------------------------------
// K=64 GEMM pass body: out_tile(96 x 64) (+)= A_tile @ W^T
// 256 threads, 41.2 KB static smem -> 4 blocks/SM, grid 521 = single wave.
// Per thread: 3 nodes (nb=3*tn, banks coprime with 32) x 8 outputs.
// Per k: 3 conflict-free scalar LDS + 2 warp-uniform LDS.128 + 24 FFMA.
// ---------------------------------------------------------------------------
template <bool ACCUM>
__device__ __forceinline__ void gemm_pass(
    const float* __restrict__ A,
    const float* __restrict__ W,
    float* __restrict__ out,
    int N)
{
    __shared__ float As[CH * ASTR];   // As[k * 97 + n], 24832 B
    __shared__ float Ws[CH * CH];     // Ws[k * 64 + o], 16384 B
    int tid = threadIdx.x;
    int node0 = blockIdx.x * NPB;

    // Stage W transposed: o fast across lanes -> STS banks = lane (conflict-
    // free). Global reads strided but W is tiny and L2-resident.
    for (int idx = tid; idx < CH * CH; idx += 256) {
        int o = idx & 63;
        int k = idx >> 6;
        Ws[k * CH + o] = __ldg(&W[o * CH + k]);
    }

    // Stage A transpose: n fast across lanes -> STS banks = lane + const.
    for (int idx4 = tid; idx4 < NPB * 16; idx4 += 256) {
        int n  = idx4 % NPB;
        int i4 = idx4 / NPB;
        int gn = node0 + n;
        float4 v = make_float4(0.f, 0.f, 0.f, 0.f);
        if (gn < N) {
            v = __ldg(reinterpret_cast<const float4*>(A + (size_t)gn * CH) + i4);
        }
        int k = i4 * 4;
        As[(k + 0) * ASTR + n] = v.x;
        As[(k + 1) * ASTR + n] = v.y;
        As[(k + 2) * ASTR + n] = v.z;
        As[(k + 3) * ASTR + n] = v.w;
    }
    __syncthreads();

    int tn = tid & 31;          // lane
    int nb = tn * 3;            // 3 consecutive nodes; 3*lane mod 32 all distinct
    int ob = (tid >> 5) * 8;    // 8 consecutive outputs (warp-uniform)

    float acc[3][8];
    #pragma unroll
    for (int j = 0; j < 3; j++)
        #pragma unroll
        for (int o = 0; o < 8; o++) acc[j][o] = 0.f;

    #pragma unroll 4
    for (int k = 0; k < CH; k++) {
        const float* ar = As + k * ASTR + nb;
        float a0 = ar[0], a1 = ar[1], a2 = ar[2];
        const float4* wr = reinterpret_cast<const float4*>(Ws + k * CH + ob);
        float4 w0 = wr[0];
        float4 w1 = wr[1];
        float w[8] = {w0.x, w0.y, w0.z, w0.w, w1.x, w1.y, w1.z, w1.w};
        #pragma unroll
        for (int o = 0; o < 8; o++) acc[0][o] += a0 * w[o];
        #pragma unroll
        for (int o = 0; o < 8; o++) acc[1][o] += a1 * w[o];
        #pragma unroll
        for (int o = 0; o < 8; o++) acc[2][o] += a2 * w[o];
    }

    #pragma unroll
    for (int j = 0; j < 3; j++) {
        int gn = node0 + nb + j;
        if (gn < N) {
            float4* orow = reinterpret_cast<float4*>(out + (size_t)gn * CH + ob);
            float4 r0 = make_float4(acc[j][0], acc[j][1], acc[j][2], acc[j][3]);
            float4 r1 = make_float4(acc[j][4], acc[j][5], acc[j][6], acc[j][7]);
            if (ACCUM) {
                float4 p0 = orow[0], p1 = orow[1];
                r0.x += p0.x; r0.y += p0.y; r0.z += p0.z; r0.w += p0.w;
                r1.x += p1.x; r1.y += p1.y; r1.z += p1.z; r1.w += p1.w;
            }
            orow[0] = r0;
            orow[1] = r1;
        }
    }
}

// Pass 1: out = x @ psi^T
__global__ void __launch_bounds__(256, 4) psi_gemm_kernel(
    const float* __restrict__ x,
    const float* __restrict__ psi,
    float* __restrict__ out,
    int N)
{
    gemm_pass<false>(x, psi, out, N);
}

// Pass 2: out += g_buf @ phi^T
__global__ void __launch_bounds__(256, 4) phi_gemm_kernel(
    const float* __restrict__ phi,
    float* __restrict__ out,
    int N)
{
    gemm_pass<true>(g_buf, phi, out, N);
}

// ---------------------------------------------------------------------------
// Launch
// ---------------------------------------------------------------------------
extern "C" void kernel_launch(void* const* d_in, const int* in_sizes, int n_in,
                              void* d_out, int out_size) {
    const float* x   = (const float*)d_in[0];
    const void*  ei  = d_in[1];
    const float* ea  = (const float*)d_in[2];
    const float* phi = (const float*)d_in[3];
    const float* psi = (const float*)d_in[4];
    float*       out = (float*)d_out;

    int N = in_sizes[0] / CH;   // 50000
    int E = in_sizes[1] / 2;    // 800000

    // 0. zero accumulator via async memset (graph-capturable) + dtype probe
    void* bufp = nullptr;
    cudaGetSymbolAddress(&bufp, g_buf);
    cudaMemsetAsync(bufp, 0, (size_t)N * CH * sizeof(float));
    probe_kernel<<<1, 32>>>((const int*)ei);

    // 1. edge scatter (16 threads per edge)
    long long tot = (long long)E * 16;
    int eblocks = (int)((tot + 255) / 256);
    edge_scatter_kernel<<<eblocks, 256>>>(x, ei, ea, E, N);

    // 2. out = x @ psi^T ; 3. out += g_buf @ phi^T
    int ngrid = (N + NPB - 1) / NPB;   // 521 <= 592 -> single wave at 4/SM
    psi_gemm_kernel<<<ngrid, 256>>>(x, psi, out, N);
    phi_gemm_kernel<<<ngrid, 256>>>(phi, out, N);
}

// round 11
// speedup vs baseline: 1.2215x; 1.2215x over previous
#include <cuda_runtime.h>
#include <math.h>

#define CH 64
#define MAX_NODES 50000
#define KS 128        // concat K dim: [x | g_buf]
#define NPB 128       // nodes per GEMM tile
#define ASTR 129      // A tile row stride (odd -> conflict-free scalar reads)
#define WSTR 68       // W tile row stride (mult of 4 -> aligned LDS.128)
#define GEMM_SMEM ((KS * ASTR + KS * WSTR) * (int)sizeof(float))  // 100864 B

// Scratch for the scatter-accumulated, scaled source features.
__device__ float g_buf[MAX_NODES * CH];
// 1 if edge_index buffer is int64, 0 if int32 (probed on device each run).
__device__ int g_is64;

// ---------------------------------------------------------------------------
// Kernel 0: probe edge_index dtype with one warp. int64 little-endian with
// values < 2^31 => every odd 32-bit word zero.
// ---------------------------------------------------------------------------
__global__ void probe_kernel(const int* __restrict__ ei32) {
    int nz = (ei32[2 * threadIdx.x + 1] != 0) ? 1 : 0;
    unsigned any = __ballot_sync(0xffffffffu, nz);
    if (threadIdx.x == 0) g_is64 = (any == 0u) ? 1 : 0;
}

// ---------------------------------------------------------------------------
// Kernel 1: edge scatter.  g_buf[dst] += ||edge_attr[e]|| * x[src]
// 16 threads per edge, one float4 per thread; leader loads metadata.
// No smem -> full occupancy; L2/LTS-bound (at its ~38us traffic floor).
// ---------------------------------------------------------------------------
__global__ void __launch_bounds__(256) edge_scatter_kernel(
    const float* __restrict__ x,
    const void* __restrict__ ei_raw,
    const float* __restrict__ ea,
    int E, int N)
{
    int t = blockIdx.x * blockDim.x + threadIdx.x;
    int e = t >> 4;
    if (e >= E) return;
    int lane = threadIdx.x & 15;
    int grpleader = threadIdx.x & 16;

    int src = 0, dst = 0;
    float scale = 0.f;
    if (lane == 0) {
        if (g_is64) {
            const long long* ei = (const long long*)ei_raw;
            src = (int)__ldg(&ei[e]);
            dst = (int)__ldg(&ei[E + e]);
        } else {
            const int* ei = (const int*)ei_raw;
            src = __ldg(&ei[e]);
            dst = __ldg(&ei[E + e]);
        }
        float a0 = __ldg(&ea[3 * e + 0]);
        float a1 = __ldg(&ea[3 * e + 1]);
        float a2 = __ldg(&ea[3 * e + 2]);
        scale = sqrtf(a0 * a0 + a1 * a1 + a2 * a2);
    }
    src   = __shfl_sync(0xffffffffu, src,   grpleader);
    dst   = __shfl_sync(0xffffffffu, dst,   grpleader);
    scale = __shfl_sync(0xffffffffu, scale, grpleader);

    if ((unsigned)src >= (unsigned)N || (unsigned)dst >= (unsigned)N) return;

    float4 v = __ldg(reinterpret_cast<const float4*>(x + (size_t)src * CH) + lane);
    v.x *= scale; v.y *= scale; v.z *= scale; v.w *= scale;

    float* addr = g_buf + (size_t)dst * CH + lane * 4;
    asm volatile("red.global.add.v4.f32 [%0], {%1, %2, %3, %4};"
                 :: "l"(addr), "f"(v.x), "f"(v.y), "f"(v.z), "f"(v.w)
                 : "memory");
}

// ---------------------------------------------------------------------------
// Kernel 2: fused GEMM   out = [x | g_buf] @ [psi ; phi]^T
// Tile: 128 nodes x 64 outputs x K=128. 512 threads -> 32 warps/SM at 2
// blocks/SM. Per thread: 2 nodes (nl, nl+64) x 8 outputs = 16 accumulators.
// Per k: 2 conflict-free scalar LDS + 2 warp-uniform LDS.128 + 16 FFMA.
// ---------------------------------------------------------------------------
extern __shared__ float smem[];

__global__ void __launch_bounds__(512, 2) fused_gemm_kernel(
    const float* __restrict__ x,
    const float* __restrict__ phi,
    const float* __restrict__ psi,
    float* __restrict__ out,
    int N)
{
    float* As = smem;                 // As[k * ASTR + n]
    float* Ws = smem + KS * ASTR;     // Ws[k * WSTR + o]
    int tid = threadIdx.x;
    int node0 = blockIdx.x * NPB;

    // Stage W: [psi ; phi] -> Ws[k][o]; coalesced LDG.
    for (int idx = tid; idx < CH * KS; idx += 512) {
        int o = idx >> 7;
        int i = idx & 127;
        float v = (i < CH) ? __ldg(&psi[o * CH + i])
                           : __ldg(&phi[o * CH + (i - CH)]);
        Ws[i * WSTR + o] = v;
    }

    // Stage A: float4 LDG from x / g_buf (coalesced), scalar STS transpose.
    for (int idx4 = tid; idx4 < NPB * 32; idx4 += 512) {
        int n  = idx4 >> 5;        // node within tile
        int i4 = idx4 & 31;        // which float4 of the 128-float concat row
        int gn = node0 + n;
        float4 v = make_float4(0.f, 0.f, 0.f, 0.f);
        if (gn < N) {
            v = (i4 < 16)
                ? __ldg(reinterpret_cast<const float4*>(x + (size_t)gn * CH) + i4)
                : __ldg(reinterpret_cast<const float4*>(g_buf + (size_t)gn * CH) + (i4 - 16));
        }
        int i = i4 * 4;
        As[(i + 0) * ASTR + n] = v.x;
        As[(i + 1) * ASTR + n] = v.y;
        As[(i + 2) * ASTR + n] = v.z;
        As[(i + 3) * ASTR + n] = v.w;
    }
    __syncthreads();

    int nl = tid & 63;          // node lane: handles nodes nl and nl+64
    int ob = (tid >> 6) * 8;    // 8 consecutive outputs (warp-uniform)

    float acc[2][8];
    #pragma unroll
    for (int j = 0; j < 2; j++)
        #pragma unroll
        for (int o = 0; o < 8; o++) acc[j][o] = 0.f;

    #pragma unroll 8
    for (int k = 0; k < KS; k++) {
        const float* ar = As + k * ASTR + nl;
        float a0 = ar[0];           // bank = (k + nl) & 31: conflict-free
        float a1 = ar[64];
        const float4* wr = reinterpret_cast<const float4*>(Ws + k * WSTR + ob);
        float4 w0 = wr[0];          // warp-uniform -> broadcast
        float4 w1 = wr[1];
        float w[8] = {w0.x, w0.y, w0.z, w0.w, w1.x, w1.y, w1.z, w1.w};
        #pragma unroll
        for (int o = 0; o < 8; o++) acc[0][o] += a0 * w[o];
        #pragma unroll
        for (int o = 0; o < 8; o++) acc[1][o] += a1 * w[o];
    }

    // Output: nodes nl and nl+64, 8 floats each -> 2 STG.128 per node,
    // coalesced across the warp.
    #pragma unroll
    for (int j = 0; j < 2; j++) {
        int gn = node0 + nl + 64 * j;
        if (gn < N) {
            float4* orow = reinterpret_cast<float4*>(out + (size_t)gn * CH + ob);
            orow[0] = make_float4(acc[j][0], acc[j][1], acc[j][2], acc[j][3]);
            orow[1] = make_float4(acc[j][4], acc[j][5], acc[j][6], acc[j][7]);
        }
    }
}

// ---------------------------------------------------------------------------
// Launch
// ---------------------------------------------------------------------------
extern "C" void kernel_launch(void* const* d_in, const int* in_sizes, int n_in,
                              void* d_out, int out_size) {
    const float* x   = (const float*)d_in[0];
    const void*  ei  = d_in[1];
    const float* ea  = (const float*)d_in[2];
    const float* phi = (const float*)d_in[3];
    const float* psi = (const float*)d_in[4];
    float*       out = (float*)d_out;

    int N = in_sizes[0] / CH;   // 50000
    int E = in_sizes[1] / 2;    // 800000

    // 0. zero accumulator via async memset (graph-capturable) + dtype probe
    void* bufp = nullptr;
    cudaGetSymbolAddress(&bufp, g_buf);
    cudaMemsetAsync(bufp, 0, (size_t)N * CH * sizeof(float));
    probe_kernel<<<1, 32>>>((const int*)ei);

    // 1. edge scatter (16 threads per edge)
    long long tot = (long long)E * 16;
    int eblocks = (int)((tot + 255) / 256);
    edge_scatter_kernel<<<eblocks, 256>>>(x, ei, ea, E, N);

    // 2. fused GEMM: out = [x | g_buf] @ [psi ; phi]^T
    cudaFuncSetAttribute(fused_gemm_kernel,
                         cudaFuncAttributeMaxDynamicSharedMemorySize,
                         GEMM_SMEM);
    fused_gemm_kernel<<<(N + NPB - 1) / NPB, 512, GEMM_SMEM>>>(x, phi, psi, out, N);
}